// round 17
// baseline (speedup 1.0000x reference)
#include <cuda_runtime.h>
#include <cuda_fp16.h>
#include <math.h>
#include <stddef.h>
#include <stdint.h>

// NOTE: harness builds via compute_103 virtual arch -> tcgen05/TMEM PTX is
// rejected by ptxas. mma.sync (HMMA) + ldmatrix is the available tensor path.

namespace {
constexpr int B = 8, T = 2048, C = 1024, H = 128;
constexpr int NR = B * T;   // 16384 rows
constexpr int LD = 12;      // smem row stride in u32 (48B rows: LDSM conflict-free)
constexpr int BUF_BYTES = 128 * LD * 4;   // one buffer of one operand array
}

// scratch (device globals: allocation-free per harness rules)
__device__ float    g_sq[NR];
__device__ float    g_sk[NR];
// packed half2 (k-pair) operands. q/k: hi only (gap-protected logits).
__device__ uint32_t g_qh[NR * 64];
__device__ uint32_t g_kh[NR * 64];
__device__ uint32_t g_vh[NR * 64], g_vl[NR * 64];   // v: hi/lo (res-critical)

// ---------------------------------------------------------------------------
__device__ __forceinline__ uint32_t smem_u32(const void* p) {
    uint32_t a;
    asm("{ .reg .u64 t; cvta.to.shared.u64 t, %1; cvt.u32.u64 %0, t; }" : "=r"(a) : "l"(p));
    return a;
}

__device__ __forceinline__ void splitH4(float4 v, uint32_t& h0, uint32_t& h1,
                                        uint32_t& l0, uint32_t& l1) {
    __half2 a = __floats2half2_rn(v.x, v.y);
    __half2 b = __floats2half2_rn(v.z, v.w);
    float2 af = __half22float2(a), bf = __half22float2(b);
    __half2 al = __floats2half2_rn(v.x - af.x, v.y - af.y);
    __half2 bl = __floats2half2_rn(v.z - bf.x, v.w - bf.y);
    h0 = *(uint32_t*)&a;  h1 = *(uint32_t*)&b;
    l0 = *(uint32_t*)&al; l1 = *(uint32_t*)&bl;
}

__device__ __forceinline__ void cvtH4(float4 v, uint32_t& h0, uint32_t& h1) {
    __half2 a = __floats2half2_rn(v.x, v.y);
    __half2 b = __floats2half2_rn(v.z, v.w);
    h0 = *(uint32_t*)&a; h1 = *(uint32_t*)&b;
}

__device__ __forceinline__ void splitH2(float a, float b, uint32_t& h, uint32_t& l) {
    __half2 hh = __floats2half2_rn(a, b);
    float2 hf = __half22float2(hh);
    __half2 ll = __floats2half2_rn(a - hf.x, b - hf.y);
    h = *(uint32_t*)&hh; l = *(uint32_t*)&ll;
}

#define MMAH(c, a, b) \
    asm volatile("mma.sync.aligned.m16n8k16.row.col.f32.f16.f16.f32 " \
        "{%0,%1,%2,%3},{%4,%5,%6,%7},{%8,%9},{%0,%1,%2,%3};" \
        : "+f"((c)[0]), "+f"((c)[1]), "+f"((c)[2]), "+f"((c)[3]) \
        : "r"((a)[0]), "r"((a)[1]), "r"((a)[2]), "r"((a)[3]), \
          "r"((b)[0]), "r"((b)[1]))

__device__ __forceinline__ void ldsm_x4(uint32_t addr, uint32_t* r) {
    asm volatile("ldmatrix.sync.aligned.m8n8.x4.shared.b16 {%0,%1,%2,%3}, [%4];"
        : "=r"(r[0]), "=r"(r[1]), "=r"(r[2]), "=r"(r[3]) : "r"(addr));
}

// 3-pass slab: hh + lh + hl (res-critical: proj_v)
__device__ __forceinline__ void mma_slab3(
    uint32_t aAh, uint32_t aAl, uint32_t aBh, uint32_t aBl,
    const uint32_t* aoff, const uint32_t* boff, float acc[4][4][4])
{
    uint32_t ah[4][4], al[4][4], bh[4][2], bl[4][2];
#pragma unroll
    for (int i = 0; i < 4; i++) {
        ldsm_x4(aAh + aoff[i], ah[i]);
        ldsm_x4(aAl + aoff[i], al[i]);
    }
#pragma unroll
    for (int p = 0; p < 2; p++) {
        uint32_t rb[4];
        ldsm_x4(aBh + boff[p], rb);
        bh[2 * p][0] = rb[0]; bh[2 * p + 1][0] = rb[1];
        bh[2 * p][1] = rb[2]; bh[2 * p + 1][1] = rb[3];
        ldsm_x4(aBl + boff[p], rb);
        bl[2 * p][0] = rb[0]; bl[2 * p + 1][0] = rb[1];
        bl[2 * p][1] = rb[2]; bl[2 * p + 1][1] = rb[3];
    }
#pragma unroll
    for (int i = 0; i < 4; i++)
#pragma unroll
        for (int j = 0; j < 4; j++) {
            MMAH(acc[i][j], ah[i], bh[j]);
            MMAH(acc[i][j], al[i], bh[j]);
            MMAH(acc[i][j], ah[i], bl[j]);
        }
}

// 2-pass slab: hh + hl (A hi only; B hi/lo) — pv
__device__ __forceinline__ void mma_slab2(
    uint32_t aAh, uint32_t aBh, uint32_t aBl,
    const uint32_t* aoff, const uint32_t* boff, float acc[4][4][4])
{
    uint32_t ah[4][4], bh[4][2], bl[4][2];
#pragma unroll
    for (int i = 0; i < 4; i++)
        ldsm_x4(aAh + aoff[i], ah[i]);
#pragma unroll
    for (int p = 0; p < 2; p++) {
        uint32_t rb[4];
        ldsm_x4(aBh + boff[p], rb);
        bh[2 * p][0] = rb[0]; bh[2 * p + 1][0] = rb[1];
        bh[2 * p][1] = rb[2]; bh[2 * p + 1][1] = rb[3];
        ldsm_x4(aBl + boff[p], rb);
        bl[2 * p][0] = rb[0]; bl[2 * p + 1][0] = rb[1];
        bl[2 * p][1] = rb[2]; bl[2 * p + 1][1] = rb[3];
    }
#pragma unroll
    for (int i = 0; i < 4; i++)
#pragma unroll
        for (int j = 0; j < 4; j++) {
            MMAH(acc[i][j], ah[i], bh[j]);
            MMAH(acc[i][j], ah[i], bl[j]);
        }
}

// 1-pass slab: hh only (gap-protected logit paths)
__device__ __forceinline__ void mma_slab1(
    uint32_t aAh, uint32_t aBh,
    const uint32_t* aoff, const uint32_t* boff, float acc[4][4][4])
{
    uint32_t ah[4][4], bh[4][2];
#pragma unroll
    for (int i = 0; i < 4; i++)
        ldsm_x4(aAh + aoff[i], ah[i]);
#pragma unroll
    for (int p = 0; p < 2; p++) {
        uint32_t rb[4];
        ldsm_x4(aBh + boff[p], rb);
        bh[2 * p][0] = rb[0]; bh[2 * p + 1][0] = rb[1];
        bh[2 * p][1] = rb[2]; bh[2 * p + 1][1] = rb[3];
    }
#pragma unroll
    for (int i = 0; i < 4; i++)
#pragma unroll
        for (int j = 0; j < 4; j++)
            MMAH(acc[i][j], ah[i], bh[j]);
}

// per-warp ldmatrix address offsets (bytes) within one operand buffer
#define MAKE_LDSM_OFFSETS()                                              \
    uint32_t aoff[4], boff[2];                                           \
    {                                                                    \
        const int l15 = lane & 15, lhi = lane >> 4;                      \
        _Pragma("unroll")                                                \
        for (int i = 0; i < 4; i++)                                      \
            aoff[i] = (uint32_t)((wm + 16 * i + l15) * 48 + lhi * 16);   \
        _Pragma("unroll")                                                \
        for (int p = 0; p < 2; p++)                                      \
            boff[p] = (uint32_t)((wn + 16 * p + l15) * 48 + lhi * 16);   \
    }

// ---------------------------------------------------------------------------
// proj q/k: 1-pass (xh * Wh). Writes hi-only halves + row sums.
__global__ __launch_bounds__(256) void proj_qk_kernel(
    const float* __restrict__ x, const float* __restrict__ Wq,
    const float* __restrict__ Wk)
{
    __shared__ uint32_t Ah[2][128 * LD];
    __shared__ uint32_t Bh[2][128 * LD];
    __shared__ float ssum[128];
    const int isQ = (blockIdx.y == 0);
    const float* W = isQ ? Wq : Wk;
    uint32_t* outh = isQ ? g_qh : g_kh;
    const int m0 = blockIdx.x * 128;
    const int tid = threadIdx.x;
    const int w = tid >> 5, lane = tid & 31;
    const int wm = (w & 1) * 64, wn = (w >> 1) * 32;
    const int g = lane >> 2, t = lane & 3;
    const int pr = tid >> 1, pc = (tid & 1) * 4;

    MAKE_LDSM_OFFSETS();
    const uint32_t bAh = smem_u32(&Ah[0][0]);
    const uint32_t bBh = smem_u32(&Bh[0][0]);

    if (tid < 128) ssum[tid] = 0.f;

    const float* ap = x + (size_t)(m0 + pr) * C + pc * 2;
    const float* bp = W + (size_t)pr * C + pc * 2;

    float4 rA0 = *(const float4*)ap, rA1 = *(const float4*)(ap + 4);
    float4 rB0 = *(const float4*)bp, rB1 = *(const float4*)(bp + 4);

    float acc[4][4][4];
#pragma unroll
    for (int i = 0; i < 4; i++)
#pragma unroll
        for (int j = 0; j < 4; j++)
#pragma unroll
            for (int q = 0; q < 4; q++) acc[i][j][q] = 0.f;

    const int NS = C / 16;
    {
        uint32_t h0, h1, h2, h3;
        cvtH4(rA0, h0, h1); cvtH4(rA1, h2, h3);
        *(uint4*)&Ah[0][pr * LD + pc] = make_uint4(h0, h1, h2, h3);
        cvtH4(rB0, h0, h1); cvtH4(rB1, h2, h3);
        *(uint4*)&Bh[0][pr * LD + pc] = make_uint4(h0, h1, h2, h3);
    }
#pragma unroll 1
    for (int s = 0; s < NS; s++) {
        const int cur = s & 1, nxt = cur ^ 1;
        const uint32_t bo = (uint32_t)(cur * BUF_BYTES);
        __syncthreads();
        if (s + 1 < NS) {
            rA0 = *(const float4*)(ap + (s + 1) * 16);
            rA1 = *(const float4*)(ap + (s + 1) * 16 + 4);
            rB0 = *(const float4*)(bp + (s + 1) * 16);
            rB1 = *(const float4*)(bp + (s + 1) * 16 + 4);
        }
        mma_slab1(bAh + bo, bBh + bo, aoff, boff, acc);
        if (s + 1 < NS) {
            uint32_t h0, h1, h2, h3;
            cvtH4(rA0, h0, h1); cvtH4(rA1, h2, h3);
            *(uint4*)&Ah[nxt][pr * LD + pc] = make_uint4(h0, h1, h2, h3);
            cvtH4(rB0, h0, h1); cvtH4(rB1, h2, h3);
            *(uint4*)&Bh[nxt][pr * LD + pc] = make_uint4(h0, h1, h2, h3);
        }
    }
    // epilogue: hi-only write + row sums
#pragma unroll
    for (int i = 0; i < 4; i++) {
        const int r0 = wm + 16 * i + g;
        float s0 = 0.f, s1 = 0.f;
#pragma unroll
        for (int j = 0; j < 4; j++) {
            const int p = (wn >> 1) + 4 * j + t;
            __half2 h2a = __floats2half2_rn(acc[i][j][0], acc[i][j][1]);
            outh[(size_t)(m0 + r0) * 64 + p] = *(uint32_t*)&h2a;
            __half2 h2b = __floats2half2_rn(acc[i][j][2], acc[i][j][3]);
            outh[(size_t)(m0 + r0 + 8) * 64 + p] = *(uint32_t*)&h2b;
            s0 += acc[i][j][0] + acc[i][j][1];
            s1 += acc[i][j][2] + acc[i][j][3];
        }
        atomicAdd(&ssum[r0], s0);
        atomicAdd(&ssum[r0 + 8], s1);
    }
    __syncthreads();
    if (tid < 128) {
        float* gs = isQ ? g_sq : g_sk;
        gs[m0 + tid] = ssum[tid];
    }
}

// ---------------------------------------------------------------------------
// proj v: 3-pass (res accuracy depends on v). Writes pre-split halves.
__global__ __launch_bounds__(256) void proj_v_kernel(
    const float* __restrict__ x, const float* __restrict__ Wv)
{
    __shared__ uint32_t Ah[2][128 * LD], Al[2][128 * LD];
    __shared__ uint32_t Bh[2][128 * LD], Bl[2][128 * LD];
    const int m0 = blockIdx.x * 128;
    const int tid = threadIdx.x;
    const int w = tid >> 5, lane = tid & 31;
    const int wm = (w & 1) * 64, wn = (w >> 1) * 32;
    const int g = lane >> 2, t = lane & 3;
    const int pr = tid >> 1, pc = (tid & 1) * 4;

    MAKE_LDSM_OFFSETS();
    const uint32_t bAh = smem_u32(&Ah[0][0]), bAl = smem_u32(&Al[0][0]);
    const uint32_t bBh = smem_u32(&Bh[0][0]), bBl = smem_u32(&Bl[0][0]);

    const float* ap = x + (size_t)(m0 + pr) * C + pc * 2;
    const float* bp = Wv + (size_t)pr * C + pc * 2;

    float4 rA0 = *(const float4*)ap, rA1 = *(const float4*)(ap + 4);
    float4 rB0 = *(const float4*)bp, rB1 = *(const float4*)(bp + 4);

    float acc[4][4][4];
#pragma unroll
    for (int i = 0; i < 4; i++)
#pragma unroll
        for (int j = 0; j < 4; j++)
#pragma unroll
            for (int q = 0; q < 4; q++) acc[i][j][q] = 0.f;

    const int NS = C / 16;
    {
        uint32_t h0, h1, h2, h3, l0, l1, l2, l3;
        splitH4(rA0, h0, h1, l0, l1); splitH4(rA1, h2, h3, l2, l3);
        *(uint4*)&Ah[0][pr * LD + pc] = make_uint4(h0, h1, h2, h3);
        *(uint4*)&Al[0][pr * LD + pc] = make_uint4(l0, l1, l2, l3);
        splitH4(rB0, h0, h1, l0, l1); splitH4(rB1, h2, h3, l2, l3);
        *(uint4*)&Bh[0][pr * LD + pc] = make_uint4(h0, h1, h2, h3);
        *(uint4*)&Bl[0][pr * LD + pc] = make_uint4(l0, l1, l2, l3);
    }
#pragma unroll 1
    for (int s = 0; s < NS; s++) {
        const int cur = s & 1, nxt = cur ^ 1;
        const uint32_t bo = (uint32_t)(cur * BUF_BYTES);
        __syncthreads();
        if (s + 1 < NS) {
            rA0 = *(const float4*)(ap + (s + 1) * 16);
            rA1 = *(const float4*)(ap + (s + 1) * 16 + 4);
            rB0 = *(const float4*)(bp + (s + 1) * 16);
            rB1 = *(const float4*)(bp + (s + 1) * 16 + 4);
        }
        mma_slab3(bAh + bo, bAl + bo, bBh + bo, bBl + bo, aoff, boff, acc);
        if (s + 1 < NS) {
            uint32_t h0, h1, h2, h3, l0, l1, l2, l3;
            splitH4(rA0, h0, h1, l0, l1); splitH4(rA1, h2, h3, l2, l3);
            *(uint4*)&Ah[nxt][pr * LD + pc] = make_uint4(h0, h1, h2, h3);
            *(uint4*)&Al[nxt][pr * LD + pc] = make_uint4(l0, l1, l2, l3);
            splitH4(rB0, h0, h1, l0, l1); splitH4(rB1, h2, h3, l2, l3);
            *(uint4*)&Bh[nxt][pr * LD + pc] = make_uint4(h0, h1, h2, h3);
            *(uint4*)&Bl[nxt][pr * LD + pc] = make_uint4(l0, l1, l2, l3);
        }
    }
#pragma unroll
    for (int i = 0; i < 4; i++) {
        const int r0 = wm + 16 * i + g;
#pragma unroll
        for (int j = 0; j < 4; j++) {
            const int p = (wn >> 1) + 4 * j + t;
            uint32_t h, l;
            splitH2(acc[i][j][0], acc[i][j][1], h, l);
            g_vh[(size_t)(m0 + r0) * 64 + p] = h;
            g_vl[(size_t)(m0 + r0) * 64 + p] = l;
            splitH2(acc[i][j][2], acc[i][j][3], h, l);
            g_vh[(size_t)(m0 + r0 + 8) * 64 + p] = h;
            g_vl[(size_t)(m0 + r0 + 8) * 64 + p] = l;
        }
    }
}

// ---------------------------------------------------------------------------
// score: raw S = qh.kh over lower-band 128x128 tiles (1-pass)
__global__ __launch_bounds__(256) void score_mma_kernel(float* __restrict__ attn)
{
    __shared__ uint32_t Ah[2][128 * LD];
    __shared__ uint32_t Bh[2][128 * LD];
    const int b = blockIdx.y;
    const int idx = blockIdx.x;
    int ti = (int)((sqrtf(8.f * (float)idx + 1.f) - 1.f) * 0.5f);
    if (ti > 15) ti = 15;
    while ((ti + 1) * (ti + 2) / 2 <= idx) ti++;
    while (ti * (ti + 1) / 2 > idx) ti--;
    const int tj = idx - ti * (ti + 1) / 2;
    const int t0 = ti * 128, s0 = tj * 128;

    const int tid = threadIdx.x;
    const int w = tid >> 5, lane = tid & 31;
    const int wm = (w & 1) * 64, wn = (w >> 1) * 32;
    const int g = lane >> 2, t = lane & 3;
    const int pr = tid >> 1, pc = (tid & 1) * 4;

    MAKE_LDSM_OFFSETS();
    const uint32_t bAh = smem_u32(&Ah[0][0]);
    const uint32_t bBh = smem_u32(&Bh[0][0]);

    const uint32_t* qh = g_qh + (size_t)(b * T + t0 + pr) * 64 + pc;
    const uint32_t* kh = g_kh + (size_t)(b * T + s0 + pr) * 64 + pc;

    uint4 rAh = *(const uint4*)qh;
    uint4 rBh = *(const uint4*)kh;

    float acc[4][4][4];
#pragma unroll
    for (int i = 0; i < 4; i++)
#pragma unroll
        for (int j = 0; j < 4; j++)
#pragma unroll
            for (int q = 0; q < 4; q++) acc[i][j][q] = 0.f;

    const int NS = H / 16;  // 8
    *(uint4*)&Ah[0][pr * LD + pc] = rAh;
    *(uint4*)&Bh[0][pr * LD + pc] = rBh;
#pragma unroll 1
    for (int s = 0; s < NS; s++) {
        const int cur = s & 1, nxt = cur ^ 1;
        const uint32_t bo = (uint32_t)(cur * BUF_BYTES);
        __syncthreads();
        if (s + 1 < NS) {
            rAh = *(const uint4*)(qh + (s + 1) * 8);
            rBh = *(const uint4*)(kh + (s + 1) * 8);
        }
        mma_slab1(bAh + bo, bBh + bo, aoff, boff, acc);
        if (s + 1 < NS) {
            *(uint4*)&Ah[nxt][pr * LD + pc] = rAh;
            *(uint4*)&Bh[nxt][pr * LD + pc] = rBh;
        }
    }
#pragma unroll
    for (int i = 0; i < 4; i++)
#pragma unroll
        for (int j = 0; j < 4; j++) {
            int row = t0 + wm + 16 * i + g;
            int col = s0 + wn + 8 * j + 2 * t;
            *(float2*)&attn[(size_t)(b * T + row) * T + col]     = make_float2(acc[i][j][0], acc[i][j][1]);
            *(float2*)&attn[(size_t)(b * T + row + 8) * T + col] = make_float2(acc[i][j][2], acc[i][j][3]);
        }
}

// ---------------------------------------------------------------------------
// softmax: in-place per row; band-only reads, pos terms folded as 3 FMA.
__global__ __launch_bounds__(256) void softmax_kernel(float* __restrict__ attn)
{
    __shared__ float red[8];
    const int r = blockIdx.x;
    const int b = r >> 11;
    const int t = r & (T - 1);
    float* row = attn + (size_t)r * T;
    const float* skrow = g_sk + (size_t)b * T;
    const int tid = threadIdx.x;
    const int c0 = tid * 8;
    const bool act = (c0 <= t);

    // lg = qk/32 + s*(sq+128t)/32 + (t/32)*sk
    const float aco = (g_sq[r] + 128.f * (float)t) * 0.03125f;
    const float tk  = (float)t * 0.03125f;

    float qk[8] = {0, 0, 0, 0, 0, 0, 0, 0};
    float sk[8] = {0, 0, 0, 0, 0, 0, 0, 0};
    if (act) {
        float4 v0 = *(const float4*)(row + c0);
        float4 v1 = *(const float4*)(row + c0 + 4);
        float4 s0 = *(const float4*)(skrow + c0);
        float4 s1 = *(const float4*)(skrow + c0 + 4);
        qk[0] = v0.x; qk[1] = v0.y; qk[2] = v0.z; qk[3] = v0.w;
        qk[4] = v1.x; qk[5] = v1.y; qk[6] = v1.z; qk[7] = v1.w;
        sk[0] = s0.x; sk[1] = s0.y; sk[2] = s0.z; sk[3] = s0.w;
        sk[4] = s1.x; sk[5] = s1.y; sk[6] = s1.z; sk[7] = s1.w;
    }

    float lg[8];
    float mx = -INFINITY;
#pragma unroll
    for (int j = 0; j < 8; j++) {
        int s = c0 + j;
        float v = fmaf((float)s, aco, fmaf(tk, sk[j], qk[j] * 0.03125f));
        lg[j] = (s <= t) ? v : -INFINITY;
        mx = fmaxf(mx, lg[j]);
    }
#pragma unroll
    for (int o = 16; o > 0; o >>= 1)
        mx = fmaxf(mx, __shfl_xor_sync(0xffffffffu, mx, o));
    if ((tid & 31) == 0) red[tid >> 5] = mx;
    __syncthreads();
    float m = red[0];
#pragma unroll
    for (int i = 1; i < 8; i++) m = fmaxf(m, red[i]);
    __syncthreads();

    float ev[8];
    float sum = 0.f;
#pragma unroll
    for (int j = 0; j < 8; j++) {
        ev[j] = __expf(lg[j] - m);
        sum += ev[j];
    }
#pragma unroll
    for (int o = 16; o > 0; o >>= 1)
        sum += __shfl_xor_sync(0xffffffffu, sum, o);
    if ((tid & 31) == 0) red[tid >> 5] = sum;
    __syncthreads();
    float tot = red[0];
#pragma unroll
    for (int i = 1; i < 8; i++) tot += red[i];
    const float rinv = 1.f / tot;

    *(float4*)(row + c0)     = make_float4(ev[0] * rinv, ev[1] * rinv, ev[2] * rinv, ev[3] * rinv);
    *(float4*)(row + c0 + 4) = make_float4(ev[4] * rinv, ev[5] * rinv, ev[6] * rinv, ev[7] * rinv);
}

// ---------------------------------------------------------------------------
// pv: res += attn_chunk @ v_chunk (2-pass: ph*vh + ph*vl; attn hi-only,
// uniform 128-wide split-K chunks, atomicAdd into zeroed res, ldmatrix).
__global__ __launch_bounds__(256) void pv_mma_kernel(
    const float* __restrict__ attn, float* __restrict__ res)
{
    __shared__ uint32_t Ah[2][128 * LD];
    __shared__ uint32_t Bh[2][128 * LD], Bl[2][128 * LD];
    const int b = blockIdx.y;
    const int idx = blockIdx.x;
    int kt = (int)((sqrtf(8.f * (float)idx + 1.f) - 1.f) * 0.5f);
    if (kt > 15) kt = 15;
    while ((kt + 1) * (kt + 2) / 2 <= idx) kt++;
    while (kt * (kt + 1) / 2 > idx) kt--;
    const int chunk = idx - kt * (kt + 1) / 2;
    const int t0 = kt * 128;
    const int sbeg = chunk * 128;
    const int NS = 8;

    const int tid = threadIdx.x;
    const int w = tid >> 5, lane = tid & 31;
    const int wm = (w & 1) * 64, wn = (w >> 1) * 32;
    const int g = lane >> 2, t = lane & 3;
    const int pr = tid >> 1, pc = (tid & 1) * 4;   // A stager
    const int sp = tid & 7, hq = tid >> 3;         // B stager: s-pair, h-quad

    MAKE_LDSM_OFFSETS();
    const uint32_t bAh = smem_u32(&Ah[0][0]);
    const uint32_t bBh = smem_u32(&Bh[0][0]), bBl = smem_u32(&Bl[0][0]);

    const float* ap = attn + (size_t)(b * T + t0 + pr) * T + sbeg + pc * 2;
    const uint32_t* vh = g_vh + (size_t)(b * T + sbeg + 2 * sp) * 64 + 2 * hq;
    const uint32_t* vl = g_vl + (size_t)(b * T + sbeg + 2 * sp) * 64 + 2 * hq;

    float4 rA0 = *(const float4*)ap, rA1 = *(const float4*)(ap + 4);
    uint2 rha = *(const uint2*)vh,   rhb = *(const uint2*)(vh + 64);
    uint2 rla = *(const uint2*)vl,   rlb = *(const uint2*)(vl + 64);

    float acc[4][4][4];
#pragma unroll
    for (int i = 0; i < 4; i++)
#pragma unroll
        for (int j = 0; j < 4; j++)
#pragma unroll
            for (int q = 0; q < 4; q++) acc[i][j][q] = 0.f;

    {
        uint32_t h0, h1, h2, h3;
        cvtH4(rA0, h0, h1); cvtH4(rA1, h2, h3);
        *(uint4*)&Ah[0][pr * LD + pc] = make_uint4(h0, h1, h2, h3);
        Bh[0][(4 * hq + 0) * LD + sp] = __byte_perm(rha.x, rhb.x, 0x5410);
        Bh[0][(4 * hq + 1) * LD + sp] = __byte_perm(rha.x, rhb.x, 0x7632);
        Bh[0][(4 * hq + 2) * LD + sp] = __byte_perm(rha.y, rhb.y, 0x5410);
        Bh[0][(4 * hq + 3) * LD + sp] = __byte_perm(rha.y, rhb.y, 0x7632);
        Bl[0][(4 * hq + 0) * LD + sp] = __byte_perm(rla.x, rlb.x, 0x5410);
        Bl[0][(4 * hq + 1) * LD + sp] = __byte_perm(rla.x, rlb.x, 0x7632);
        Bl[0][(4 * hq + 2) * LD + sp] = __byte_perm(rla.y, rlb.y, 0x5410);
        Bl[0][(4 * hq + 3) * LD + sp] = __byte_perm(rla.y, rlb.y, 0x7632);
    }
#pragma unroll 1
    for (int s = 0; s < NS; s++) {
        const int cur = s & 1, nxt = cur ^ 1;
        const uint32_t bo = (uint32_t)(cur * BUF_BYTES);
        __syncthreads();
        if (s + 1 < NS) {
            rA0 = *(const float4*)(ap + (s + 1) * 16);
            rA1 = *(const float4*)(ap + (s + 1) * 16 + 4);
            const uint32_t* vh2 = vh + (size_t)(s + 1) * 16 * 64;
            const uint32_t* vl2 = vl + (size_t)(s + 1) * 16 * 64;
            rha = *(const uint2*)vh2; rhb = *(const uint2*)(vh2 + 64);
            rla = *(const uint2*)vl2; rlb = *(const uint2*)(vl2 + 64);
        }
        mma_slab2(bAh + bo, bBh + bo, bBl + bo, aoff, boff, acc);
        if (s + 1 < NS) {
            uint32_t h0, h1, h2, h3;
            cvtH4(rA0, h0, h1); cvtH4(rA1, h2, h3);
            *(uint4*)&Ah[nxt][pr * LD + pc] = make_uint4(h0, h1, h2, h3);
            Bh[nxt][(4 * hq + 0) * LD + sp] = __byte_perm(rha.x, rhb.x, 0x5410);
            Bh[nxt][(4 * hq + 1) * LD + sp] = __byte_perm(rha.x, rhb.x, 0x7632);
            Bh[nxt][(4 * hq + 2) * LD + sp] = __byte_perm(rha.y, rhb.y, 0x5410);
            Bh[nxt][(4 * hq + 3) * LD + sp] = __byte_perm(rha.y, rhb.y, 0x7632);
            Bl[nxt][(4 * hq + 0) * LD + sp] = __byte_perm(rla.x, rlb.x, 0x5410);
            Bl[nxt][(4 * hq + 1) * LD + sp] = __byte_perm(rla.x, rlb.x, 0x7632);
            Bl[nxt][(4 * hq + 2) * LD + sp] = __byte_perm(rla.y, rlb.y, 0x5410);
            Bl[nxt][(4 * hq + 3) * LD + sp] = __byte_perm(rla.y, rlb.y, 0x7632);
        }
    }
#pragma unroll
    for (int i = 0; i < 4; i++)
#pragma unroll
        for (int j = 0; j < 4; j++) {
            int row = t0 + wm + 16 * i + g;
            int col = wn + 8 * j + 2 * t;
            float* p0 = res + (size_t)(b * T + row) * H + col;
            float* p1 = res + (size_t)(b * T + row + 8) * H + col;
            atomicAdd(p0,     acc[i][j][0]);
            atomicAdd(p0 + 1, acc[i][j][1]);
            atomicAdd(p1,     acc[i][j][2]);
            atomicAdd(p1 + 1, acc[i][j][3]);
        }
}

// ---------------------------------------------------------------------------
// Stream fork for proj_v overlap. Created lazily on the (uncaptured)
// correctness call; captured calls only record/wait events (capture-legal).
static cudaStream_t s_vstream = nullptr;
static cudaEvent_t  s_evFork = nullptr, s_evVDone = nullptr;

extern "C" void kernel_launch(void* const* d_in, const int* in_sizes, int n_in,
                              void* d_out, int out_size)
{
    const float* x  = (const float*)d_in[0];
    const float* Wq = (const float*)d_in[1];
    const float* Wk = (const float*)d_in[2];
    const float* Wv = (const float*)d_in[3];
    float* res  = (float*)d_out;
    float* attn = res + (size_t)B * T * H;

    if (s_vstream == nullptr) {
        cudaStreamCreateWithFlags(&s_vstream, cudaStreamNonBlocking);
        cudaEventCreateWithFlags(&s_evFork, cudaEventDisableTiming);
        cudaEventCreateWithFlags(&s_evVDone, cudaEventDisableTiming);
    }

    // fork: proj_v depends only on x; runs concurrent with qk/score/softmax
    cudaEventRecord(s_evFork, 0);
    cudaStreamWaitEvent(s_vstream, s_evFork, 0);
    proj_v_kernel<<<NR / 128, 256, 0, s_vstream>>>(x, Wv);
    cudaEventRecord(s_evVDone, s_vstream);

    cudaMemsetAsync(res, 0, (size_t)NR * H * sizeof(float));
    proj_qk_kernel<<<dim3(NR / 128, 2), 256>>>(x, Wq, Wk);
    score_mma_kernel<<<dim3(136, 8), 256>>>(attn);
    softmax_kernel<<<NR, 256>>>(attn);

    // join: pv needs v halves
    cudaStreamWaitEvent(0, s_evVDone, 0);
    pv_mma_kernel<<<dim3(136, 8), 256>>>(attn, res);
}